// round 7
// baseline (speedup 1.0000x reference)
#include <cuda_runtime.h>
#include <math.h>

typedef unsigned long long u64;

#define NJ 4800
#define FEAT 15
#define HH 3
#define D1 64
#define F1 192
#define D2 128
#define F2 384
#define C1 65     // D1+1 (last column = scalar weight sum)
#define C2 129    // D2+1
#define GOUT 143  // D2 + FEAT
#define HID 64
#define BATCH 32
#define JOBS 150
#define CHUNK 96
#define NCHUNK 50 // 96*50 = 4800
#define NBQ 10    // bsearch blocks per head fused into chunk kernel (10*480=4800)

// ---------------- scratch (static __device__ globals) ----------------
__device__ float g_hh1[NJ * F1];
__device__ float g_s1[NJ * HH];
__device__ u64   g_pk1[HH * NJ];
__device__ float g_tsort1[HH * NJ];
__device__ int   g_perm1[HH * NJ];
__device__ float g_csum1[HH * NCHUNK * 2 * C1];
__device__ float g_pref1[HH * (NJ + 1) * 2 * C1];
__device__ int   g_lo1[NJ * HH];
__device__ float g_h1cat[NJ * F1];
__device__ float g_wt2[2 * HH * F1];   // [sel(src/dst)][h][f]
__device__ float g_hh2[NJ * F2];
__device__ float g_s2[NJ * HH];
__device__ u64   g_pk2[HH * NJ];
__device__ float g_tsort2[HH * NJ];
__device__ int   g_perm2[HH * NJ];
__device__ float g_csum2[HH * NCHUNK * 2 * C2];
__device__ float g_pref2[HH * (NJ + 1) * 2 * C2];
__device__ int   g_lo2[NJ * HH];
__device__ float g_g[NJ * GOUT];
__device__ float g_f1[NJ * 128];
__device__ float g_f2[NJ * HID];

// ---- kernel 1 (fused): hh1 = flat@W1, s1/t1/pk1 scores, w~2 precompute ------
__global__ void k_feat_fused(const float* __restrict__ X, const float* __restrict__ W,
                             const float* __restrict__ asrc1, const float* __restrict__ adst1,
                             const float* __restrict__ W2, const float* __restrict__ asrc2,
                             const float* __restrict__ adst2,
                             float* __restrict__ O, float* __restrict__ s,
                             u64* __restrict__ pk, float* __restrict__ wt2) {
    int tid = threadIdx.x;  // 192
    if (blockIdx.x >= NJ / 8) {
        // w~2 precompute: 6 blocks, one per (sel, h); thread f does a 128-dot
        int b = blockIdx.x - NJ / 8;
        int sel = b / HH, h = b - sel * HH;
        const float* a2 = sel ? adst2 : asrc2;
        float acc = 0.f;
#pragma unroll 4
        for (int d = 0; d < D2; d++)
            acc += W2[tid * F2 + h * D2 + d] * a2[h * D2 + d];
        wt2[(sel * HH + h) * F1 + tid] = acc;
        return;
    }
    __shared__ float xs[8 * FEAT];
    __shared__ float red_s[6 * 8], red_t[6 * 8];  // [warp][row]
    int n0 = blockIdx.x * 8;
    if (tid < 8 * FEAT) xs[tid] = X[n0 * FEAT + tid];
    __syncthreads();
    float wv[FEAT];
#pragma unroll
    for (int f = 0; f < FEAT; f++) wv[f] = W[f * F1 + tid];
    float asv = asrc1[tid], adv = adst1[tid];   // layout [h*64+d] == tid
    int warp = tid >> 5, lane = tid & 31;
    float acc[8];
#pragma unroll
    for (int r = 0; r < 8; r++) {
        float a = 0.f;
#pragma unroll
        for (int f = 0; f < FEAT; f++) a += xs[r * FEAT + f] * wv[f];
        O[(n0 + r) * F1 + tid] = a;
        acc[r] = a;
    }
#pragma unroll
    for (int r = 0; r < 8; r++) {
        float ps = acc[r] * asv, pt = acc[r] * adv;
#pragma unroll
        for (int o = 16; o > 0; o >>= 1) {
            ps += __shfl_xor_sync(0xFFFFFFFFu, ps, o);
            pt += __shfl_xor_sync(0xFFFFFFFFu, pt, o);
        }
        if (lane == 0) { red_s[warp * 8 + r] = ps; red_t[warp * 8 + r] = pt; }
    }
    __syncthreads();
    if (tid < 24) {  // r = tid/3, h = tid%3 (2 warps per head)
        int r = tid / 3, h = tid - r * 3;
        float sv = red_s[(2 * h) * 8 + r] + red_s[(2 * h + 1) * 8 + r];
        float tv = red_t[(2 * h) * 8 + r] + red_t[(2 * h + 1) * 8 + r];
        int n = n0 + r;
        s[n * HH + h] = sv;
        unsigned int u = __float_as_uint(tv);
        u = (u & 0x80000000u) ? ~u : (u | 0x80000000u);
        pk[h * NJ + n] = (((u64)u) << 32) | (unsigned int)n;
    }
}

// ---------------- sort-by-rank-counting (exact, tie-broken by index) ---------
__global__ void k_rank(const u64* __restrict__ pk, float* __restrict__ tsort,
                       int* __restrict__ perm) {
    __shared__ int part[768];
    int h = blockIdx.x;
    int tj = threadIdx.x % 96;
    int sp = threadIdx.x / 96;
    int j = blockIdx.y * 96 + tj;
    const u64* base = pk + h * NJ;
    u64 mykey = base[j];
    int cnt = 0;
    int b0 = sp * (NJ / 8), b1 = b0 + (NJ / 8);
#pragma unroll 8
    for (int kk = b0; kk < b1; kk++) cnt += (base[kk] < mykey) ? 1 : 0;
    part[threadIdx.x] = cnt;
    __syncthreads();
    if (sp == 0) {
        int rank = part[tj];
#pragma unroll
        for (int q = 1; q < 8; q++) rank += part[q * 96 + tj];
        unsigned int u = (unsigned int)(mykey >> 32);
        unsigned int bits = (u & 0x80000000u) ? (u ^ 0x80000000u) : ~u;
        tsort[h * NJ + rank] = __uint_as_float(bits);
        perm[h * NJ + rank] = (int)(mykey & 0xFFFFFFFFu);
    }
}

// ---- chunk partial sums (KS-way split) + fused smem-cached binary searches --
template <int D, int F, int KS>
__global__ void k_chunk_bs(const float* __restrict__ hh, const float* __restrict__ tsort,
                           const int* __restrict__ perm, const float* __restrict__ s,
                           float* __restrict__ csum, int* __restrict__ lo_out) {
    const int C = D + 1, TC = 2 * C, SEG = CHUNK / KS;
    int h = blockIdx.x, ch = blockIdx.y, tid = threadIdx.x;
    int nthr = blockDim.x;
    if (ch >= NCHUNK) {
        // bsearch branch: cache whole sorted head in smem, search at LDS latency
        __shared__ float tss[NJ];
        for (int k = tid; k < NJ; k += nthr) tss[k] = tsort[h * NJ + k];
        __syncthreads();
        int qbase = (ch - NCHUNK) * (NJ / NBQ);
        for (int q = tid; q < NJ / NBQ; q += nthr) {
            int i = qbase + q;
            float thr = -s[i * HH + h];
            int lo = 0, hi = NJ;
            while (lo < hi) {
                int m = (lo + hi) >> 1;
                if (tss[m] < thr) lo = m + 1; else hi = m;
            }
            lo_out[i * HH + h] = lo;
        }
        return;
    }
    __shared__ float wp[CHUNK], wn[CHUNK];
    __shared__ int jj[CHUNK];
    __shared__ float part[KS * TC];
    if (tid < CHUNK) {
        float tv = tsort[h * NJ + ch * CHUNK + tid];
        wp[tid] = expf(tv);
        wn[tid] = expf(0.2f * tv);
        jj[tid] = perm[h * NJ + ch * CHUNK + tid];
    }
    __syncthreads();
    if (tid >= KS * TC) return;
    int ks = tid / TC, rem = tid - ks * TC;
    int b = rem / C, c = rem - b * C;
    const float* ws = b ? wn : wp;
    float acc = 0.f;
    int k0 = ks * SEG;
#pragma unroll 8
    for (int kk = 0; kk < SEG; kk++) {
        int kq = k0 + kk;
        float v = (c < D) ? hh[jj[kq] * F + h * D + c] : 1.0f;
        acc += ws[kq] * v;
    }
    part[tid] = acc;
    __syncthreads();
    if (ks == 0) {
        float tot = acc;
#pragma unroll
        for (int q = 1; q < KS; q++) tot += part[q * TC + rem];
        csum[((h * NCHUNK + ch) * 2 + b) * C + c] = tot;
    }
}

// ---------------- segmented exclusive prefix rows + totals row ---------------
template <int D, int F, int KS>
__global__ void k_scanv(const float* __restrict__ hh, const float* __restrict__ tsort,
                        const int* __restrict__ perm, const float* __restrict__ csum,
                        float* __restrict__ pref) {
    const int C = D + 1, TC = 2 * C, SEG = CHUNK / KS, R = 2 * C;
    __shared__ float wp[CHUNK], wn[CHUNK];
    __shared__ int jj[CHUNK];
    __shared__ float part[KS * TC];
    __shared__ float basem[TC];
    int h = blockIdx.x, ch = blockIdx.y, tid = threadIdx.x;
    int ks = tid / TC, rem = tid - ks * TC;
    int b = rem / C, c = rem - b * C;
    bool act = (tid < KS * TC);

    int nprev = (ch < NCHUNK) ? ch : NCHUNK;
    float base = 0.f;
    if (act && ks == 0) {
        for (int p = 0; p < nprev; p++) base += csum[((h * NCHUNK + p) * 2 + b) * C + c];
    }
    if (ch == NCHUNK) {
        if (act && ks == 0) pref[(h * (NJ + 1) + NJ) * R + rem] = base;
        return;
    }
    if (tid < CHUNK) {
        float tv = tsort[h * NJ + ch * CHUNK + tid];
        wp[tid] = expf(tv);
        wn[tid] = expf(0.2f * tv);
        jj[tid] = perm[h * NJ + ch * CHUNK + tid];
    }
    if (act && ks == 0) basem[rem] = base;
    __syncthreads();
    if (!act) return;

    const float* ws = b ? wn : wp;
    float acc = 0.f;
    int k0 = ks * SEG;
#pragma unroll 8
    for (int kk = 0; kk < SEG; kk++) {
        int kq = k0 + kk;
        float v = (c < D) ? hh[jj[kq] * F + h * D + c] : 1.0f;
        acc += ws[kq] * v;
    }
    part[tid] = acc;
    __syncthreads();

    float run = basem[rem];
#pragma unroll
    for (int q = 0; q < KS; q++)
        if (q < ks) run += part[q * TC + rem];
    int rowbase = h * (NJ + 1) + ch * CHUNK;
    for (int kk = 0; kk < SEG; kk++) {
        int kq = k0 + kk;
        pref[(rowbase + kq) * R + rem] = run;  // exclusive
        float v = (c < D) ? hh[jj[kq] * F + h * D + c] : 1.0f;
        run += ws[kq] * v;
    }
}

// ---- layer-1 query (fused): GAT out + ELU -> h1cat, plus s2/t2/pk2 scores ---
__global__ void k_query1_fused(const float* __restrict__ s, const int* __restrict__ lo_in,
                               const float* __restrict__ pref, const float* __restrict__ wt2,
                               float* __restrict__ out, float* __restrict__ s2,
                               u64* __restrict__ pk2) {
    const int C = C1, R = 2 * C1;
    __shared__ int lo_s[HH];
    __shared__ float Es_s[HH], en_s[HH];
    __shared__ float red[6][6];  // [warp][sel*3+h]
    int i = blockIdx.x, tid = threadIdx.x;  // 192
    if (tid < HH) {
        float sv = s[i * HH + tid];
        lo_s[tid] = lo_in[i * HH + tid];
        Es_s[tid] = expf(sv);
        en_s[tid] = expf(0.2f * sv);
    }
    __syncthreads();
    int h = tid / D1, d = tid % D1;
    const float* prow = pref + (h * (NJ + 1) + lo_s[h]) * R;
    const float* trow = pref + (h * (NJ + 1) + NJ) * R;
    float Es = Es_s[h], en = en_s[h];
    float num = Es * (trow[d] - prow[d]) + en * prow[C + d];
    float den = Es * (trow[D1] - prow[D1]) + en * prow[C + D1];
    float v = num / den;
    v = (v > 0.f) ? v : expm1f(v);  // ELU
    out[i * F1 + tid] = v;

    // fused layer-2 scores: s2[h2] = h1c_row . wt2[0][h2], t2 = . wt2[1][h2]
    int warp = tid >> 5, lane = tid & 31;
    float p[6];
#pragma unroll
    for (int q = 0; q < 6; q++) p[q] = v * wt2[q * F1 + tid];
#pragma unroll
    for (int o = 16; o > 0; o >>= 1)
#pragma unroll
        for (int q = 0; q < 6; q++) p[q] += __shfl_xor_sync(0xFFFFFFFFu, p[q], o);
    if (lane == 0)
#pragma unroll
        for (int q = 0; q < 6; q++) red[warp][q] = p[q];
    __syncthreads();
    if (tid < 6) {
        float tot = red[0][tid];
#pragma unroll
        for (int w = 1; w < 6; w++) tot += red[w][tid];
        int sel = tid / HH, h2 = tid - sel * HH;
        if (sel == 0) {
            s2[i * HH + h2] = tot;
        } else {
            unsigned int u = __float_as_uint(tot);
            u = (u & 0x80000000u) ? ~u : (u | 0x80000000u);
            pk2[h2 * NJ + i] = (((u64)u) << 32) | (unsigned int)i;
        }
    }
}

// ---------------- layer-2 query: GAT output, head-mean, concat flat ----------
__global__ void k_query2(const float* __restrict__ s, const int* __restrict__ lo_in,
                         const float* __restrict__ pref, const float* __restrict__ obs,
                         float* __restrict__ g) {
    const int C = C2, R = 2 * C2;
    __shared__ int lo_s[HH];
    __shared__ float Es_s[HH], en_s[HH];
    __shared__ float sv_s[F2];
    int i = blockIdx.x, tid = threadIdx.x;  // 384
    if (tid < HH) {
        float sv = s[i * HH + tid];
        lo_s[tid] = lo_in[i * HH + tid];
        Es_s[tid] = expf(sv);
        en_s[tid] = expf(0.2f * sv);
    }
    __syncthreads();
    int h = tid / D2, d = tid % D2;
    const float* prow = pref + (h * (NJ + 1) + lo_s[h]) * R;
    const float* trow = pref + (h * (NJ + 1) + NJ) * R;
    float Es = Es_s[h], en = en_s[h];
    float num = Es * (trow[d] - prow[d]) + en * prow[C + d];
    float den = Es * (trow[D2] - prow[D2]) + en * prow[C + D2];
    sv_s[tid] = num / den;
    __syncthreads();
    if (tid < D2) {
        g[i * GOUT + tid] = (sv_s[tid] + sv_s[D2 + tid] + sv_s[2 * D2 + tid]) * (1.0f / 3.0f);
    } else if (tid < D2 + FEAT) {
        g[i * GOUT + tid] = obs[i * FEAT + (tid - D2)];
    }
}

// ---------------- generic fp32 tiled GEMM: C = A[M,K] @ B[K,N] ---------------
template <int EPI>
__global__ void k_gemm(int M, int K, int Nn, const float* __restrict__ A,
                       const float* __restrict__ Bm, const float* __restrict__ bias,
                       float* __restrict__ Cm) {
    const int BM = 64, BN = 64, BK = 16;
    __shared__ float As[BK][BM + 1];
    __shared__ float Bs[BK][BN];
    int tid = threadIdx.x;
    int tc = tid % 16, tr = tid / 16;
    int row0 = blockIdx.y * BM, col0 = blockIdx.x * BN;
    float acc[4][4] = {};
    for (int k0 = 0; k0 < K; k0 += BK) {
        for (int l = tid; l < BM * BK; l += 256) {
            int r = l / BK, c = l % BK;
            int gr = row0 + r, gk = k0 + c;
            As[c][r] = (gr < M && gk < K) ? A[gr * K + gk] : 0.f;
        }
        for (int l = tid; l < BK * BN; l += 256) {
            int r = l / BN, c = l % BN;
            int gk = k0 + r, gc = col0 + c;
            Bs[r][c] = (gk < K && gc < Nn) ? Bm[gk * Nn + gc] : 0.f;
        }
        __syncthreads();
#pragma unroll
        for (int kk = 0; kk < BK; kk++) {
            float a[4], b[4];
#pragma unroll
            for (int m = 0; m < 4; m++) a[m] = As[kk][tr * 4 + m];
#pragma unroll
            for (int n = 0; n < 4; n++) b[n] = Bs[kk][tc * 4 + n];
#pragma unroll
            for (int m = 0; m < 4; m++)
#pragma unroll
                for (int n = 0; n < 4; n++) acc[m][n] += a[m] * b[n];
        }
        __syncthreads();
    }
#pragma unroll
    for (int m = 0; m < 4; m++) {
        int gr = row0 + tr * 4 + m;
        if (gr >= M) continue;
#pragma unroll
        for (int n = 0; n < 4; n++) {
            int gc = col0 + tc * 4 + n;
            if (gc >= Nn) continue;
            float v = acc[m][n];
            if (EPI) { v += bias[gc]; v = fmaxf(v, 0.f); }
            Cm[gr * Nn + gc] = v;
        }
    }
}

// ---------------- fused mean-pool + mask copy --------------------------------
__global__ void k_pool_copy(const float* __restrict__ f2, const float* __restrict__ mask,
                            float* __restrict__ out, int mcount) {
    if (blockIdx.x < BATCH) {
        int b = blockIdx.x, d = threadIdx.x;
        if (d >= HID) return;
        float acc = 0.f;
        for (int j = 0; j < JOBS; j++) acc += f2[(b * JOBS + j) * HID + d];
        out[b * HID + d] = acc * (1.0f / JOBS);
    } else {
        int i = (blockIdx.x - BATCH) * 256 + threadIdx.x;
        if (i < mcount) out[BATCH * HID + i] = mask[i];
    }
}

// ---------------- launch ------------------------------------------------------
extern "C" void kernel_launch(void* const* d_in, const int* in_sizes, int n_in,
                              void* d_out, int out_size) {
    const float* obs    = (const float*)d_in[0];
    const float* mask   = (const float*)d_in[1];
    const float* W1     = (const float*)d_in[2];
    const float* a_src1 = (const float*)d_in[3];
    const float* a_dst1 = (const float*)d_in[4];
    const float* W2     = (const float*)d_in[5];
    const float* a_src2 = (const float*)d_in[6];
    const float* a_dst2 = (const float*)d_in[7];
    const float* P1     = (const float*)d_in[8];
    const float* b1     = (const float*)d_in[9];
    const float* P2     = (const float*)d_in[10];
    const float* b2     = (const float*)d_in[11];
    float* out = (float*)d_out;

    float *hh1, *s1, *ts1, *cs1, *pf1, *h1c, *wt2, *hh2, *s2, *ts2, *cs2, *pf2, *gg, *f1, *f2;
    u64 *pk1, *pk2;
    int *pm1, *pm2, *lo1, *lo2;
    cudaGetSymbolAddress((void**)&hh1, g_hh1);
    cudaGetSymbolAddress((void**)&s1, g_s1);
    cudaGetSymbolAddress((void**)&pk1, g_pk1);
    cudaGetSymbolAddress((void**)&ts1, g_tsort1);
    cudaGetSymbolAddress((void**)&pm1, g_perm1);
    cudaGetSymbolAddress((void**)&cs1, g_csum1);
    cudaGetSymbolAddress((void**)&pf1, g_pref1);
    cudaGetSymbolAddress((void**)&lo1, g_lo1);
    cudaGetSymbolAddress((void**)&h1c, g_h1cat);
    cudaGetSymbolAddress((void**)&wt2, g_wt2);
    cudaGetSymbolAddress((void**)&hh2, g_hh2);
    cudaGetSymbolAddress((void**)&s2, g_s2);
    cudaGetSymbolAddress((void**)&pk2, g_pk2);
    cudaGetSymbolAddress((void**)&ts2, g_tsort2);
    cudaGetSymbolAddress((void**)&pm2, g_perm2);
    cudaGetSymbolAddress((void**)&cs2, g_csum2);
    cudaGetSymbolAddress((void**)&pf2, g_pref2);
    cudaGetSymbolAddress((void**)&lo2, g_lo2);
    cudaGetSymbolAddress((void**)&gg, g_g);
    cudaGetSymbolAddress((void**)&f1, g_f1);
    cudaGetSymbolAddress((void**)&f2, g_f2);

    // 1: features + layer-1 scores + w~2 precompute
    k_feat_fused<<<NJ / 8 + 6, F1>>>(obs, W1, a_src1, a_dst1, W2, a_src2, a_dst2,
                                     hh1, s1, pk1, wt2);
    // 2: sort layer 1
    k_rank<<<dim3(HH, NJ / 96), 768>>>(pk1, ts1, pm1);
    // 3: chunk sums + binary searches (layer 1)
    k_chunk_bs<D1, F1, 4><<<dim3(HH, NCHUNK + NBQ), 520>>>(hh1, ts1, pm1, s1, cs1, lo1);
    // 4: prefix scan (layer 1)
    k_scanv<D1, F1, 4><<<dim3(HH, NCHUNK + 1), 520>>>(hh1, ts1, pm1, cs1, pf1);
    // 5: layer-1 query + ELU + layer-2 scores
    k_query1_fused<<<NJ, F1>>>(s1, lo1, pf1, wt2, h1c, s2, pk2);
    // 6: hh2 = h1cat @ W2
    k_gemm<0><<<dim3(F2 / 64, NJ / 64), 256>>>(NJ, F1, F2, h1c, W2, nullptr, hh2);
    // 7: sort layer 2
    k_rank<<<dim3(HH, NJ / 96), 768>>>(pk2, ts2, pm2);
    // 8: chunk sums + binary searches (layer 2)
    k_chunk_bs<D2, F2, 2><<<dim3(HH, NCHUNK + NBQ), 520>>>(hh2, ts2, pm2, s2, cs2, lo2);
    // 9: prefix scan (layer 2)
    k_scanv<D2, F2, 2><<<dim3(HH, NCHUNK + 1), 520>>>(hh2, ts2, pm2, cs2, pf2);
    // 10: layer-2 query + head mean + concat
    k_query2<<<NJ, F2>>>(s2, lo2, pf2, obs, gg);
    // 11-12: dense head
    k_gemm<1><<<dim3(128 / 64, NJ / 64), 256>>>(NJ, GOUT, 128, gg, P1, b1, f1);
    k_gemm<1><<<dim3(HID / 64, NJ / 64), 256>>>(NJ, 128, HID, f1, P2, b2, f2);
    // 13: pool + mask passthrough
    int mrem = out_size - BATCH * HID;
    int mc = 0;
    if (mrem > 0 && n_in > 1) mc = in_sizes[1] < mrem ? in_sizes[1] : mrem;
    k_pool_copy<<<BATCH + (mc + 255) / 256, 256>>>(f2, mask, out, mc);
}

// round 8
// speedup vs baseline: 1.4563x; 1.4563x over previous
#include <cuda_runtime.h>
#include <math.h>

typedef unsigned long long u64;

#define NJ 4800
#define FEAT 15
#define HH 3
#define D1 64
#define F1 192
#define D2 128
#define F2 384
#define C1 65     // D1+1 (last column = scalar weight sum)
#define C2 129    // D2+1
#define GOUT 143  // D2 + FEAT
#define HID 64
#define BATCH 32
#define JOBS 150
#define CHUNK 96
#define NCHUNK 50 // 96*50 = 4800
#define NBQ 4     // bsearch blocks per head (4*1200=4800)

// ---------------- scratch (static __device__ globals) ----------------
__device__ float g_hh1[NJ * F1];
__device__ float g_s1[NJ * HH];
__device__ u64   g_pk1[HH * NJ];
__device__ float g_tsort1[HH * NJ];
__device__ int   g_perm1[HH * NJ];
__device__ float g_csum1[HH * NCHUNK * 2 * C1];
__device__ float g_pref1[HH * (NJ + 1) * 2 * C1];
__device__ int   g_lo1[NJ * HH];
__device__ float g_h1cat[NJ * F1];
__device__ float g_hh2[NJ * F2];
__device__ float g_s2[NJ * HH];
__device__ u64   g_pk2[HH * NJ];
__device__ float g_tsort2[HH * NJ];
__device__ int   g_perm2[HH * NJ];
__device__ float g_csum2[HH * NCHUNK * 2 * C2];
__device__ float g_pref2[HH * (NJ + 1) * 2 * C2];
__device__ int   g_lo2[NJ * HH];
__device__ float g_g[NJ * GOUT];
__device__ float g_f1[NJ * 128];
__device__ float g_f2[NJ * HID];

// ---------------- kernel 1: hh1 = flat @ W1  ([4800,15] x [15,192]) ----------
__global__ void k_feat(const float* __restrict__ X, const float* __restrict__ W,
                       float* __restrict__ O) {
    __shared__ float xs[8 * FEAT];
    int n0 = blockIdx.x * 8;
    int tid = threadIdx.x;
    if (tid < 8 * FEAT) xs[tid] = X[n0 * FEAT + tid];
    __syncthreads();
    float wv[FEAT];
#pragma unroll
    for (int f = 0; f < FEAT; f++) wv[f] = W[f * F1 + tid];
#pragma unroll
    for (int r = 0; r < 8; r++) {
        float acc = 0.f;
#pragma unroll
        for (int f = 0; f < FEAT; f++) acc += xs[r * FEAT + f] * wv[f];
        O[(n0 + r) * F1 + tid] = acc;
    }
}

// ---------------- s,t scores + packed sort keys ----------------
template <int D, int F>
__global__ void k_st(const float* __restrict__ hh, const float* __restrict__ asrc,
                     const float* __restrict__ adst, float* __restrict__ s,
                     u64* __restrict__ pk) {
    int w = blockIdx.x * 4 + (threadIdx.x >> 5);
    int lane = threadIdx.x & 31;
    int n = w / HH, h = w % HH;
    float sv = 0.f, tv = 0.f;
#pragma unroll
    for (int d = lane; d < D; d += 32) {
        float v = hh[n * F + h * D + d];
        sv += v * asrc[h * D + d];
        tv += v * adst[h * D + d];
    }
#pragma unroll
    for (int o = 16; o > 0; o >>= 1) {
        sv += __shfl_xor_sync(0xFFFFFFFFu, sv, o);
        tv += __shfl_xor_sync(0xFFFFFFFFu, tv, o);
    }
    if (lane == 0) {
        s[n * HH + h] = sv;
        unsigned int u = __float_as_uint(tv);
        u = (u & 0x80000000u) ? ~u : (u | 0x80000000u);  // orderable transform
        pk[h * NJ + n] = (((u64)u) << 32) | (unsigned int)n;
    }
}

// ---------------- sort-by-rank-counting (exact, tie-broken by index) ---------
__global__ void k_rank(const u64* __restrict__ pk, float* __restrict__ tsort,
                       int* __restrict__ perm) {
    // grid (HH, NJ/96); block 768 = 96 elements x 8 range-splits
    __shared__ int part[768];
    int h = blockIdx.x;
    int tj = threadIdx.x % 96;
    int sp = threadIdx.x / 96;
    int j = blockIdx.y * 96 + tj;
    const u64* base = pk + h * NJ;
    u64 mykey = base[j];
    int cnt = 0;
    int b0 = sp * (NJ / 8), b1 = b0 + (NJ / 8);
#pragma unroll 8
    for (int kk = b0; kk < b1; kk++) cnt += (base[kk] < mykey) ? 1 : 0;
    part[threadIdx.x] = cnt;
    __syncthreads();
    if (sp == 0) {
        int rank = part[tj];
#pragma unroll
        for (int q = 1; q < 8; q++) rank += part[q * 96 + tj];
        unsigned int u = (unsigned int)(mykey >> 32);
        unsigned int bits = (u & 0x80000000u) ? (u ^ 0x80000000u) : ~u;  // inverse
        tsort[h * NJ + rank] = __uint_as_float(bits);
        perm[h * NJ + rank] = (int)(mykey & 0xFFFFFFFFu);
    }
}

// ---------------- binary searches, sorted keys cached in smem ----------------
__global__ void k_bsearch(const float* __restrict__ s, const float* __restrict__ tsort,
                          int* __restrict__ lo_out) {
    // grid (HH, NBQ); block 512; each block: cache head's sorted keys, do NJ/NBQ searches
    __shared__ float tss[NJ];
    int h = blockIdx.x, tid = threadIdx.x;
    for (int k = tid; k < NJ; k += 512) tss[k] = tsort[h * NJ + k];
    __syncthreads();
    int qbase = blockIdx.y * (NJ / NBQ);
    for (int q = tid; q < NJ / NBQ; q += 512) {
        int i = qbase + q;
        float thr = -s[i * HH + h];
        int lo = 0, hi = NJ;
        while (lo < hi) {
            int m = (lo + hi) >> 1;
            if (tss[m] < thr) lo = m + 1; else hi = m;
        }
        lo_out[i * HH + h] = lo;
    }
}

// ---------------- chunk partial sums, KS-way k-split -------------------------
template <int D, int F, int KS>
__global__ void k_chunkv(const float* __restrict__ hh, const float* __restrict__ tsort,
                         const int* __restrict__ perm, float* __restrict__ csum) {
    // grid (HH, NCHUNK); block KS * 2*(D+1)
    const int C = D + 1, TC = 2 * C, SEG = CHUNK / KS;
    __shared__ float wp[CHUNK], wn[CHUNK];
    __shared__ int jj[CHUNK];
    __shared__ float part[KS * TC];
    int h = blockIdx.x, ch = blockIdx.y, tid = threadIdx.x;
    if (tid < CHUNK) {
        float tv = tsort[h * NJ + ch * CHUNK + tid];
        wp[tid] = expf(tv);
        wn[tid] = expf(0.2f * tv);
        jj[tid] = perm[h * NJ + ch * CHUNK + tid];
    }
    __syncthreads();
    int ks = tid / TC, rem = tid - ks * TC;
    int b = rem / C, c = rem - b * C;
    const float* ws = b ? wn : wp;
    float acc = 0.f;
    int k0 = ks * SEG;
#pragma unroll 8
    for (int kk = 0; kk < SEG; kk++) {
        int kq = k0 + kk;
        float v = (c < D) ? hh[jj[kq] * F + h * D + c] : 1.0f;
        acc += ws[kq] * v;
    }
    part[tid] = acc;
    __syncthreads();
    if (ks == 0) {
        float tot = acc;
#pragma unroll
        for (int q = 1; q < KS; q++) tot += part[q * TC + rem];
        csum[((h * NCHUNK + ch) * 2 + b) * C + c] = tot;
    }
}

// ---- segmented exclusive prefix rows + totals row (base-sum parallelized) ---
template <int D, int F, int KS>
__global__ void k_scanv(const float* __restrict__ hh, const float* __restrict__ tsort,
                        const int* __restrict__ perm, const float* __restrict__ csum,
                        float* __restrict__ pref) {
    // grid (HH, NCHUNK+1); block KS * 2*(D+1). pref[h][k][b][c], row NJ = totals
    const int C = D + 1, TC = 2 * C, SEG = CHUNK / KS, R = 2 * C;
    const int PER = (NCHUNK + KS - 1) / KS;
    __shared__ float wp[CHUNK], wn[CHUNK];
    __shared__ int jj[CHUNK];
    __shared__ float part[KS * TC];
    int h = blockIdx.x, ch = blockIdx.y, tid = threadIdx.x;
    int ks = tid / TC, rem = tid - ks * TC;
    int b = rem / C, c = rem - b * C;

    // base prefix of prior chunks, split across KS groups
    int nprev = (ch < NCHUNK) ? ch : NCHUNK;
    int p0 = ks * PER, p1 = p0 + PER;
    if (p1 > nprev) p1 = nprev;
    float bp = 0.f;
    for (int p = p0; p < p1; p++) bp += csum[((h * NCHUNK + p) * 2 + b) * C + c];
    part[tid] = bp;
    if (tid < CHUNK && ch < NCHUNK) {
        float tv = tsort[h * NJ + ch * CHUNK + tid];
        wp[tid] = expf(tv);
        wn[tid] = expf(0.2f * tv);
        jj[tid] = perm[h * NJ + ch * CHUNK + tid];
    }
    __syncthreads();
    float base = 0.f;
#pragma unroll
    for (int q = 0; q < KS; q++) base += part[q * TC + rem];

    if (ch == NCHUNK) {  // totals row (== exclusive prefix at k=NJ)
        if (ks == 0) pref[(h * (NJ + 1) + NJ) * R + rem] = base;
        return;
    }
    __syncthreads();  // part reuse below

    // phase 1: per-segment sums (parallel)
    const float* ws = b ? wn : wp;
    float acc = 0.f;
    int k0 = ks * SEG;
#pragma unroll 8
    for (int kk = 0; kk < SEG; kk++) {
        int kq = k0 + kk;
        float v = (c < D) ? hh[jj[kq] * F + h * D + c] : 1.0f;
        acc += ws[kq] * v;
    }
    part[tid] = acc;
    __syncthreads();

    // phase 2: each segment scans its SEG elements from base + prior segments
    float run = base;
#pragma unroll
    for (int q = 0; q < KS; q++)
        if (q < ks) run += part[q * TC + rem];
    int rowbase = h * (NJ + 1) + ch * CHUNK;
    for (int kk = 0; kk < SEG; kk++) {
        int kq = k0 + kk;
        pref[(rowbase + kq) * R + rem] = run;  // exclusive
        float v = (c < D) ? hh[jj[kq] * F + h * D + c] : 1.0f;
        run += ws[kq] * v;
    }
}

// ---------------- layer-1 query: GAT output + ELU -> h1cat -------------------
__global__ void k_query1(const float* __restrict__ s, const int* __restrict__ lo_in,
                         const float* __restrict__ pref, float* __restrict__ out) {
    const int C = C1, R = 2 * C1;
    __shared__ int lo_s[HH];
    __shared__ float Es_s[HH], en_s[HH];
    int i = blockIdx.x, tid = threadIdx.x;  // 192
    if (tid < HH) {
        float sv = s[i * HH + tid];
        lo_s[tid] = lo_in[i * HH + tid];
        Es_s[tid] = expf(sv);
        en_s[tid] = expf(0.2f * sv);
    }
    __syncthreads();
    int h = tid / D1, d = tid % D1;
    const float* prow = pref + (h * (NJ + 1) + lo_s[h]) * R;
    const float* trow = pref + (h * (NJ + 1) + NJ) * R;
    float Es = Es_s[h], en = en_s[h];
    float num = Es * (trow[d] - prow[d]) + en * prow[C + d];
    float den = Es * (trow[D1] - prow[D1]) + en * prow[C + D1];
    float v = num / den;
    out[i * F1 + tid] = (v > 0.f) ? v : expm1f(v);  // ELU
}

// ---------------- layer-2 query: GAT output, head-mean, concat flat ----------
__global__ void k_query2(const float* __restrict__ s, const int* __restrict__ lo_in,
                         const float* __restrict__ pref, const float* __restrict__ obs,
                         float* __restrict__ g) {
    const int C = C2, R = 2 * C2;
    __shared__ int lo_s[HH];
    __shared__ float Es_s[HH], en_s[HH];
    __shared__ float sv_s[F2];
    int i = blockIdx.x, tid = threadIdx.x;  // 384
    if (tid < HH) {
        float sv = s[i * HH + tid];
        lo_s[tid] = lo_in[i * HH + tid];
        Es_s[tid] = expf(sv);
        en_s[tid] = expf(0.2f * sv);
    }
    __syncthreads();
    int h = tid / D2, d = tid % D2;
    const float* prow = pref + (h * (NJ + 1) + lo_s[h]) * R;
    const float* trow = pref + (h * (NJ + 1) + NJ) * R;
    float Es = Es_s[h], en = en_s[h];
    float num = Es * (trow[d] - prow[d]) + en * prow[C + d];
    float den = Es * (trow[D2] - prow[D2]) + en * prow[C + D2];
    sv_s[tid] = num / den;
    __syncthreads();
    if (tid < D2) {
        g[i * GOUT + tid] = (sv_s[tid] + sv_s[D2 + tid] + sv_s[2 * D2 + tid]) * (1.0f / 3.0f);
    } else if (tid < D2 + FEAT) {
        g[i * GOUT + tid] = obs[i * FEAT + (tid - D2)];
    }
}

// ---------------- generic fp32 tiled GEMM: C = A[M,K] @ B[K,N] ---------------
template <int EPI>  // EPI=1: += bias, relu
__global__ void k_gemm(int M, int K, int Nn, const float* __restrict__ A,
                       const float* __restrict__ Bm, const float* __restrict__ bias,
                       float* __restrict__ Cm) {
    const int BM = 64, BN = 64, BK = 16;
    __shared__ float As[BK][BM + 1];
    __shared__ float Bs[BK][BN];
    int tid = threadIdx.x;           // 256 threads
    int tc = tid % 16, tr = tid / 16;
    int row0 = blockIdx.y * BM, col0 = blockIdx.x * BN;
    float acc[4][4] = {};
    for (int k0 = 0; k0 < K; k0 += BK) {
        for (int l = tid; l < BM * BK; l += 256) {
            int r = l / BK, c = l % BK;
            int gr = row0 + r, gk = k0 + c;
            As[c][r] = (gr < M && gk < K) ? A[gr * K + gk] : 0.f;
        }
        for (int l = tid; l < BK * BN; l += 256) {
            int r = l / BN, c = l % BN;
            int gk = k0 + r, gc = col0 + c;
            Bs[r][c] = (gk < K && gc < Nn) ? Bm[gk * Nn + gc] : 0.f;
        }
        __syncthreads();
#pragma unroll
        for (int kk = 0; kk < BK; kk++) {
            float a[4], b[4];
#pragma unroll
            for (int m = 0; m < 4; m++) a[m] = As[kk][tr * 4 + m];
#pragma unroll
            for (int n = 0; n < 4; n++) b[n] = Bs[kk][tc * 4 + n];
#pragma unroll
            for (int m = 0; m < 4; m++)
#pragma unroll
                for (int n = 0; n < 4; n++) acc[m][n] += a[m] * b[n];
        }
        __syncthreads();
    }
#pragma unroll
    for (int m = 0; m < 4; m++) {
        int gr = row0 + tr * 4 + m;
        if (gr >= M) continue;
#pragma unroll
        for (int n = 0; n < 4; n++) {
            int gc = col0 + tc * 4 + n;
            if (gc >= Nn) continue;
            float v = acc[m][n];
            if (EPI) { v += bias[gc]; v = fmaxf(v, 0.f); }
            Cm[gr * Nn + gc] = v;
        }
    }
}

// ---------------- fused mean-pool + mask copy --------------------------------
__global__ void k_pool_copy(const float* __restrict__ f2, const float* __restrict__ mask,
                            float* __restrict__ out, int mcount) {
    if (blockIdx.x < BATCH) {
        int b = blockIdx.x, d = threadIdx.x;
        if (d >= HID) return;
        float acc = 0.f;
        for (int j = 0; j < JOBS; j++) acc += f2[(b * JOBS + j) * HID + d];
        out[b * HID + d] = acc * (1.0f / JOBS);
    } else {
        int i = (blockIdx.x - BATCH) * 256 + threadIdx.x;
        if (i < mcount) out[BATCH * HID + i] = mask[i];
    }
}

// ---------------- launch ------------------------------------------------------
extern "C" void kernel_launch(void* const* d_in, const int* in_sizes, int n_in,
                              void* d_out, int out_size) {
    const float* obs    = (const float*)d_in[0];
    const float* mask   = (const float*)d_in[1];
    const float* W1     = (const float*)d_in[2];
    const float* a_src1 = (const float*)d_in[3];
    const float* a_dst1 = (const float*)d_in[4];
    const float* W2     = (const float*)d_in[5];
    const float* a_src2 = (const float*)d_in[6];
    const float* a_dst2 = (const float*)d_in[7];
    const float* P1     = (const float*)d_in[8];
    const float* b1     = (const float*)d_in[9];
    const float* P2     = (const float*)d_in[10];
    const float* b2     = (const float*)d_in[11];
    float* out = (float*)d_out;

    float *hh1, *s1, *ts1, *cs1, *pf1, *h1c, *hh2, *s2, *ts2, *cs2, *pf2, *gg, *f1, *f2;
    u64 *pk1, *pk2;
    int *pm1, *pm2, *lo1, *lo2;
    cudaGetSymbolAddress((void**)&hh1, g_hh1);
    cudaGetSymbolAddress((void**)&s1, g_s1);
    cudaGetSymbolAddress((void**)&pk1, g_pk1);
    cudaGetSymbolAddress((void**)&ts1, g_tsort1);
    cudaGetSymbolAddress((void**)&pm1, g_perm1);
    cudaGetSymbolAddress((void**)&cs1, g_csum1);
    cudaGetSymbolAddress((void**)&pf1, g_pref1);
    cudaGetSymbolAddress((void**)&lo1, g_lo1);
    cudaGetSymbolAddress((void**)&h1c, g_h1cat);
    cudaGetSymbolAddress((void**)&hh2, g_hh2);
    cudaGetSymbolAddress((void**)&s2, g_s2);
    cudaGetSymbolAddress((void**)&pk2, g_pk2);
    cudaGetSymbolAddress((void**)&ts2, g_tsort2);
    cudaGetSymbolAddress((void**)&pm2, g_perm2);
    cudaGetSymbolAddress((void**)&cs2, g_csum2);
    cudaGetSymbolAddress((void**)&pf2, g_pref2);
    cudaGetSymbolAddress((void**)&lo2, g_lo2);
    cudaGetSymbolAddress((void**)&gg, g_g);
    cudaGetSymbolAddress((void**)&f1, g_f1);
    cudaGetSymbolAddress((void**)&f2, g_f2);

    // Layer 1
    k_feat<<<NJ / 8, F1>>>(obs, W1, hh1);
    k_st<D1, F1><<<NJ * HH / 4, 128>>>(hh1, a_src1, a_dst1, s1, pk1);
    k_rank<<<dim3(HH, NJ / 96), 768>>>(pk1, ts1, pm1);
    k_bsearch<<<dim3(HH, NBQ), 512>>>(s1, ts1, lo1);
    k_chunkv<D1, F1, 4><<<dim3(HH, NCHUNK), 4 * 2 * C1>>>(hh1, ts1, pm1, cs1);
    k_scanv<D1, F1, 4><<<dim3(HH, NCHUNK + 1), 4 * 2 * C1>>>(hh1, ts1, pm1, cs1, pf1);
    k_query1<<<NJ, F1>>>(s1, lo1, pf1, h1c);

    // hh2 = h1cat @ W2
    k_gemm<0><<<dim3(F2 / 64, NJ / 64), 256>>>(NJ, F1, F2, h1c, W2, nullptr, hh2);

    // Layer 2
    k_st<D2, F2><<<NJ * HH / 4, 128>>>(hh2, a_src2, a_dst2, s2, pk2);
    k_rank<<<dim3(HH, NJ / 96), 768>>>(pk2, ts2, pm2);
    k_bsearch<<<dim3(HH, NBQ), 512>>>(s2, ts2, lo2);
    k_chunkv<D2, F2, 2><<<dim3(HH, NCHUNK), 2 * 2 * C2>>>(hh2, ts2, pm2, cs2);
    k_scanv<D2, F2, 2><<<dim3(HH, NCHUNK + 1), 2 * 2 * C2>>>(hh2, ts2, pm2, cs2, pf2);
    k_query2<<<NJ, F2>>>(s2, lo2, pf2, obs, gg);

    // Dense head
    k_gemm<1><<<dim3(128 / 64, NJ / 64), 256>>>(NJ, GOUT, 128, gg, P1, b1, f1);
    k_gemm<1><<<dim3(HID / 64, NJ / 64), 256>>>(NJ, 128, HID, f1, P2, b2, f2);

    // pool + mask passthrough
    int mrem = out_size - BATCH * HID;
    int mc = 0;
    if (mrem > 0 && n_in > 1) mc = in_sizes[1] < mrem ? in_sizes[1] : mrem;
    k_pool_copy<<<BATCH + (mc + 255) / 256, 256>>>(f2, mask, out, mc);
}

// round 9
// speedup vs baseline: 1.5367x; 1.0552x over previous
#include <cuda_runtime.h>
#include <math.h>

typedef unsigned long long u64;

#define NJ 4800
#define FEAT 15
#define HH 3
#define D1 64
#define F1 192
#define D2 128
#define F2 384
#define C1 65     // D1+1 (last column = scalar weight sum)
#define C2 129    // D2+1
#define GOUT 143  // D2 + FEAT
#define HID 64
#define BATCH 32
#define JOBS 150
#define CHUNK 96
#define NCHUNK 50 // 96*50 = 4800

// ---------------- scratch (static __device__ globals) ----------------
__device__ float g_hh1[NJ * F1];
__device__ float g_s1[NJ * HH];
__device__ u64   g_pk1[HH * NJ];
__device__ float g_tsort1[HH * NJ];
__device__ int   g_perm1[HH * NJ];
__device__ float g_csum1[HH * NCHUNK * 2 * C1];
__device__ float g_cseg1[HH * NCHUNK * 4 * 2 * C1];
__device__ float g_pref1[HH * (NJ + 1) * 2 * C1];
__device__ int   g_lo1[NJ * HH];
__device__ float g_h1cat[NJ * F1];
__device__ float g_hh2[NJ * F2];
__device__ float g_s2[NJ * HH];
__device__ u64   g_pk2[HH * NJ];
__device__ float g_tsort2[HH * NJ];
__device__ int   g_perm2[HH * NJ];
__device__ float g_csum2[HH * NCHUNK * 2 * C2];
__device__ float g_cseg2[HH * NCHUNK * 2 * 2 * C2];
__device__ float g_pref2[HH * (NJ + 1) * 2 * C2];
__device__ int   g_lo2[NJ * HH];
__device__ float g_g[NJ * GOUT];
__device__ float g_f1[NJ * 128];
__device__ float g_f2[NJ * HID];

// ---------------- kernel 1: hh1 = flat @ W1  ([4800,15] x [15,192]) ----------
__global__ void k_feat(const float* __restrict__ X, const float* __restrict__ W,
                       float* __restrict__ O) {
    __shared__ float xs[8 * FEAT];
    int n0 = blockIdx.x * 8;
    int tid = threadIdx.x;
    if (tid < 8 * FEAT) xs[tid] = X[n0 * FEAT + tid];
    __syncthreads();
    float wv[FEAT];
#pragma unroll
    for (int f = 0; f < FEAT; f++) wv[f] = W[f * F1 + tid];
#pragma unroll
    for (int r = 0; r < 8; r++) {
        float acc = 0.f;
#pragma unroll
        for (int f = 0; f < FEAT; f++) acc += xs[r * FEAT + f] * wv[f];
        O[(n0 + r) * F1 + tid] = acc;
    }
}

// ---------------- s,t scores + packed sort keys ----------------
template <int D, int F>
__global__ void k_st(const float* __restrict__ hh, const float* __restrict__ asrc,
                     const float* __restrict__ adst, float* __restrict__ s,
                     u64* __restrict__ pk) {
    int w = blockIdx.x * 4 + (threadIdx.x >> 5);
    int lane = threadIdx.x & 31;
    int n = w / HH, h = w % HH;
    float sv = 0.f, tv = 0.f;
#pragma unroll
    for (int d = lane; d < D; d += 32) {
        float v = hh[n * F + h * D + d];
        sv += v * asrc[h * D + d];
        tv += v * adst[h * D + d];
    }
#pragma unroll
    for (int o = 16; o > 0; o >>= 1) {
        sv += __shfl_xor_sync(0xFFFFFFFFu, sv, o);
        tv += __shfl_xor_sync(0xFFFFFFFFu, tv, o);
    }
    if (lane == 0) {
        s[n * HH + h] = sv;
        unsigned int u = __float_as_uint(tv);
        u = (u & 0x80000000u) ? ~u : (u | 0x80000000u);  // orderable transform
        pk[h * NJ + n] = (((u64)u) << 32) | (unsigned int)n;
    }
}

// ---- sort-by-rank-counting + fused threshold rank (replaces binary search) --
__global__ void k_rank(const u64* __restrict__ pk, const float* __restrict__ s,
                       float* __restrict__ tsort, int* __restrict__ perm,
                       int* __restrict__ lo_out) {
    // grid (HH, NJ/96); block 768 = 96 elements x 8 range-splits
    // counts packed: low 16 bits = sort rank, high 16 bits = #{t_j < -s_i}
    __shared__ unsigned int part[768];
    int h = blockIdx.x;
    int tj = threadIdx.x % 96;
    int sp = threadIdx.x / 96;
    int j = blockIdx.y * 96 + tj;
    const u64* base = pk + h * NJ;
    u64 mykey = base[j];
    float thr = -s[j * HH + h];
    unsigned int tu = __float_as_uint(thr);
    tu = (tu & 0x80000000u) ? ~tu : (tu | 0x80000000u);
    u64 thrkey = ((u64)tu) << 32;  // key < thrkey  <=>  t_val < thr (strict)
    unsigned int cnt = 0, cnt2 = 0;
    int b0 = sp * (NJ / 8), b1 = b0 + (NJ / 8);
#pragma unroll 8
    for (int kk = b0; kk < b1; kk++) {
        u64 k = base[kk];
        cnt  += (k < mykey)  ? 1u : 0u;
        cnt2 += (k < thrkey) ? 1u : 0u;
    }
    part[threadIdx.x] = cnt | (cnt2 << 16);
    __syncthreads();
    if (sp == 0) {
        unsigned int tot = part[tj];
#pragma unroll
        for (int q = 1; q < 8; q++) tot += part[q * 96 + tj];
        int rank = (int)(tot & 0xFFFFu);
        int lo = (int)(tot >> 16);
        unsigned int u = (unsigned int)(mykey >> 32);
        unsigned int bits = (u & 0x80000000u) ? (u ^ 0x80000000u) : ~u;  // inverse
        tsort[h * NJ + rank] = __uint_as_float(bits);
        perm[h * NJ + rank] = (int)(mykey & 0xFFFFFFFFu);
        lo_out[j * HH + h] = lo;
    }
}

// ---- chunk sums, KS-way k-split; writes chunk totals AND per-segment sums ---
template <int D, int F, int KS>
__global__ void k_chunkv(const float* __restrict__ hh, const float* __restrict__ tsort,
                         const int* __restrict__ perm, float* __restrict__ csum,
                         float* __restrict__ cseg) {
    // grid (HH, NCHUNK); block KS * 2*(D+1)
    const int C = D + 1, TC = 2 * C, SEG = CHUNK / KS;
    __shared__ float wp[CHUNK], wn[CHUNK];
    __shared__ int jj[CHUNK];
    __shared__ float part[KS * TC];
    int h = blockIdx.x, ch = blockIdx.y, tid = threadIdx.x;
    if (tid < CHUNK) {
        float tv = tsort[h * NJ + ch * CHUNK + tid];
        wp[tid] = expf(tv);
        wn[tid] = expf(0.2f * tv);
        jj[tid] = perm[h * NJ + ch * CHUNK + tid];
    }
    __syncthreads();
    int ks = tid / TC, rem = tid - ks * TC;
    int b = rem / C, c = rem - b * C;
    const float* ws = b ? wn : wp;
    float acc = 0.f;
    int k0 = ks * SEG;
#pragma unroll 8
    for (int kk = 0; kk < SEG; kk++) {
        int kq = k0 + kk;
        float v = (c < D) ? hh[jj[kq] * F + h * D + c] : 1.0f;
        acc += ws[kq] * v;
    }
    part[tid] = acc;
    cseg[((h * NCHUNK + ch) * KS + ks) * TC + rem] = acc;
    __syncthreads();
    if (ks == 0) {
        float tot = acc;
#pragma unroll
        for (int q = 1; q < KS; q++) tot += part[q * TC + rem];
        csum[((h * NCHUNK + ch) * 2 + b) * C + c] = tot;
    }
}

// ---- segmented exclusive prefix rows + totals row (reads cseg, no recompute)-
template <int D, int F, int KS>
__global__ void k_scanv(const float* __restrict__ hh, const float* __restrict__ tsort,
                        const int* __restrict__ perm, const float* __restrict__ csum,
                        const float* __restrict__ cseg, float* __restrict__ pref) {
    // grid (HH, NCHUNK+1); block KS * 2*(D+1). pref[h][k][b][c], row NJ = totals
    const int C = D + 1, TC = 2 * C, SEG = CHUNK / KS, R = 2 * C;
    const int PER = (NCHUNK + KS - 1) / KS;
    __shared__ float wp[CHUNK], wn[CHUNK];
    __shared__ int jj[CHUNK];
    __shared__ float part[KS * TC];
    int h = blockIdx.x, ch = blockIdx.y, tid = threadIdx.x;
    int ks = tid / TC, rem = tid - ks * TC;
    int b = rem / C, c = rem - b * C;

    // base prefix of prior chunks, split across KS groups
    int nprev = (ch < NCHUNK) ? ch : NCHUNK;
    int p0 = ks * PER, p1 = p0 + PER;
    if (p1 > nprev) p1 = nprev;
    float bp = 0.f;
    for (int p = p0; p < p1; p++) bp += csum[((h * NCHUNK + p) * 2 + b) * C + c];
    part[tid] = bp;
    if (tid < CHUNK && ch < NCHUNK) {
        float tv = tsort[h * NJ + ch * CHUNK + tid];
        wp[tid] = expf(tv);
        wn[tid] = expf(0.2f * tv);
        jj[tid] = perm[h * NJ + ch * CHUNK + tid];
    }
    __syncthreads();
    float base = 0.f;
#pragma unroll
    for (int q = 0; q < KS; q++) base += part[q * TC + rem];

    if (ch == NCHUNK) {  // totals row (== exclusive prefix at k=NJ)
        if (ks == 0) pref[(h * (NJ + 1) + NJ) * R + rem] = base;
        return;
    }

    // start of this segment = base + prior-segment sums within the chunk (from cseg)
    float run = base;
    for (int q = 0; q < ks; q++)
        run += cseg[((h * NCHUNK + ch) * KS + q) * TC + rem];

    const float* ws = b ? wn : wp;
    int k0 = ks * SEG;
    int rowbase = h * (NJ + 1) + ch * CHUNK;
    for (int kk = 0; kk < SEG; kk++) {
        int kq = k0 + kk;
        pref[(rowbase + kq) * R + rem] = run;  // exclusive
        float v = (c < D) ? hh[jj[kq] * F + h * D + c] : 1.0f;
        run += ws[kq] * v;
    }
}

// ---------------- layer-1 query: GAT output + ELU -> h1cat -------------------
__global__ void k_query1(const float* __restrict__ s, const int* __restrict__ lo_in,
                         const float* __restrict__ pref, float* __restrict__ out) {
    const int C = C1, R = 2 * C1;
    __shared__ int lo_s[HH];
    __shared__ float Es_s[HH], en_s[HH];
    int i = blockIdx.x, tid = threadIdx.x;  // 192
    if (tid < HH) {
        float sv = s[i * HH + tid];
        lo_s[tid] = lo_in[i * HH + tid];
        Es_s[tid] = expf(sv);
        en_s[tid] = expf(0.2f * sv);
    }
    __syncthreads();
    int h = tid / D1, d = tid % D1;
    const float* prow = pref + (h * (NJ + 1) + lo_s[h]) * R;
    const float* trow = pref + (h * (NJ + 1) + NJ) * R;
    float Es = Es_s[h], en = en_s[h];
    float num = Es * (trow[d] - prow[d]) + en * prow[C + d];
    float den = Es * (trow[D1] - prow[D1]) + en * prow[C + D1];
    float v = num / den;
    out[i * F1 + tid] = (v > 0.f) ? v : expm1f(v);  // ELU
}

// ---------------- layer-2 query: GAT output, head-mean, concat flat ----------
__global__ void k_query2(const float* __restrict__ s, const int* __restrict__ lo_in,
                         const float* __restrict__ pref, const float* __restrict__ obs,
                         float* __restrict__ g) {
    const int C = C2, R = 2 * C2;
    __shared__ int lo_s[HH];
    __shared__ float Es_s[HH], en_s[HH];
    __shared__ float sv_s[F2];
    int i = blockIdx.x, tid = threadIdx.x;  // 384
    if (tid < HH) {
        float sv = s[i * HH + tid];
        lo_s[tid] = lo_in[i * HH + tid];
        Es_s[tid] = expf(sv);
        en_s[tid] = expf(0.2f * sv);
    }
    __syncthreads();
    int h = tid / D2, d = tid % D2;
    const float* prow = pref + (h * (NJ + 1) + lo_s[h]) * R;
    const float* trow = pref + (h * (NJ + 1) + NJ) * R;
    float Es = Es_s[h], en = en_s[h];
    float num = Es * (trow[d] - prow[d]) + en * prow[C + d];
    float den = Es * (trow[D2] - prow[D2]) + en * prow[C + D2];
    sv_s[tid] = num / den;
    __syncthreads();
    if (tid < D2) {
        g[i * GOUT + tid] = (sv_s[tid] + sv_s[D2 + tid] + sv_s[2 * D2 + tid]) * (1.0f / 3.0f);
    } else if (tid < D2 + FEAT) {
        g[i * GOUT + tid] = obs[i * FEAT + (tid - D2)];
    }
}

// ---------------- generic fp32 tiled GEMM: C = A[M,K] @ B[K,N] ---------------
template <int EPI>  // EPI=1: += bias, relu
__global__ void k_gemm(int M, int K, int Nn, const float* __restrict__ A,
                       const float* __restrict__ Bm, const float* __restrict__ bias,
                       float* __restrict__ Cm) {
    const int BM = 64, BN = 64, BK = 16;
    __shared__ float As[BK][BM + 1];
    __shared__ float Bs[BK][BN];
    int tid = threadIdx.x;           // 256 threads
    int tc = tid % 16, tr = tid / 16;
    int row0 = blockIdx.y * BM, col0 = blockIdx.x * BN;
    float acc[4][4] = {};
    for (int k0 = 0; k0 < K; k0 += BK) {
        for (int l = tid; l < BM * BK; l += 256) {
            int r = l / BK, c = l % BK;
            int gr = row0 + r, gk = k0 + c;
            As[c][r] = (gr < M && gk < K) ? A[gr * K + gk] : 0.f;
        }
        for (int l = tid; l < BK * BN; l += 256) {
            int r = l / BN, c = l % BN;
            int gk = k0 + r, gc = col0 + c;
            Bs[r][c] = (gk < K && gc < Nn) ? Bm[gk * Nn + gc] : 0.f;
        }
        __syncthreads();
#pragma unroll
        for (int kk = 0; kk < BK; kk++) {
            float a[4], b[4];
#pragma unroll
            for (int m = 0; m < 4; m++) a[m] = As[kk][tr * 4 + m];
#pragma unroll
            for (int n = 0; n < 4; n++) b[n] = Bs[kk][tc * 4 + n];
#pragma unroll
            for (int m = 0; m < 4; m++)
#pragma unroll
                for (int n = 0; n < 4; n++) acc[m][n] += a[m] * b[n];
        }
        __syncthreads();
    }
#pragma unroll
    for (int m = 0; m < 4; m++) {
        int gr = row0 + tr * 4 + m;
        if (gr >= M) continue;
#pragma unroll
        for (int n = 0; n < 4; n++) {
            int gc = col0 + tc * 4 + n;
            if (gc >= Nn) continue;
            float v = acc[m][n];
            if (EPI) { v += bias[gc]; v = fmaxf(v, 0.f); }
            Cm[gr * Nn + gc] = v;
        }
    }
}

// ---------------- fused mean-pool + mask copy --------------------------------
__global__ void k_pool_copy(const float* __restrict__ f2, const float* __restrict__ mask,
                            float* __restrict__ out, int mcount) {
    if (blockIdx.x < BATCH) {
        int b = blockIdx.x, d = threadIdx.x;
        if (d >= HID) return;
        float acc = 0.f;
        for (int j = 0; j < JOBS; j++) acc += f2[(b * JOBS + j) * HID + d];
        out[b * HID + d] = acc * (1.0f / JOBS);
    } else {
        int i = (blockIdx.x - BATCH) * 256 + threadIdx.x;
        if (i < mcount) out[BATCH * HID + i] = mask[i];
    }
}

// ---------------- launch ------------------------------------------------------
extern "C" void kernel_launch(void* const* d_in, const int* in_sizes, int n_in,
                              void* d_out, int out_size) {
    const float* obs    = (const float*)d_in[0];
    const float* mask   = (const float*)d_in[1];
    const float* W1     = (const float*)d_in[2];
    const float* a_src1 = (const float*)d_in[3];
    const float* a_dst1 = (const float*)d_in[4];
    const float* W2     = (const float*)d_in[5];
    const float* a_src2 = (const float*)d_in[6];
    const float* a_dst2 = (const float*)d_in[7];
    const float* P1     = (const float*)d_in[8];
    const float* b1     = (const float*)d_in[9];
    const float* P2     = (const float*)d_in[10];
    const float* b2     = (const float*)d_in[11];
    float* out = (float*)d_out;

    float *hh1, *s1, *ts1, *cs1, *cg1, *pf1, *h1c, *hh2, *s2, *ts2, *cs2, *cg2, *pf2, *gg, *f1, *f2;
    u64 *pk1, *pk2;
    int *pm1, *pm2, *lo1, *lo2;
    cudaGetSymbolAddress((void**)&hh1, g_hh1);
    cudaGetSymbolAddress((void**)&s1, g_s1);
    cudaGetSymbolAddress((void**)&pk1, g_pk1);
    cudaGetSymbolAddress((void**)&ts1, g_tsort1);
    cudaGetSymbolAddress((void**)&pm1, g_perm1);
    cudaGetSymbolAddress((void**)&cs1, g_csum1);
    cudaGetSymbolAddress((void**)&cg1, g_cseg1);
    cudaGetSymbolAddress((void**)&pf1, g_pref1);
    cudaGetSymbolAddress((void**)&lo1, g_lo1);
    cudaGetSymbolAddress((void**)&h1c, g_h1cat);
    cudaGetSymbolAddress((void**)&hh2, g_hh2);
    cudaGetSymbolAddress((void**)&s2, g_s2);
    cudaGetSymbolAddress((void**)&pk2, g_pk2);
    cudaGetSymbolAddress((void**)&ts2, g_tsort2);
    cudaGetSymbolAddress((void**)&pm2, g_perm2);
    cudaGetSymbolAddress((void**)&cs2, g_csum2);
    cudaGetSymbolAddress((void**)&cg2, g_cseg2);
    cudaGetSymbolAddress((void**)&pf2, g_pref2);
    cudaGetSymbolAddress((void**)&lo2, g_lo2);
    cudaGetSymbolAddress((void**)&gg, g_g);
    cudaGetSymbolAddress((void**)&f1, g_f1);
    cudaGetSymbolAddress((void**)&f2, g_f2);

    // Layer 1
    k_feat<<<NJ / 8, F1>>>(obs, W1, hh1);
    k_st<D1, F1><<<NJ * HH / 4, 128>>>(hh1, a_src1, a_dst1, s1, pk1);
    k_rank<<<dim3(HH, NJ / 96), 768>>>(pk1, s1, ts1, pm1, lo1);
    k_chunkv<D1, F1, 4><<<dim3(HH, NCHUNK), 4 * 2 * C1>>>(hh1, ts1, pm1, cs1, cg1);
    k_scanv<D1, F1, 4><<<dim3(HH, NCHUNK + 1), 4 * 2 * C1>>>(hh1, ts1, pm1, cs1, cg1, pf1);
    k_query1<<<NJ, F1>>>(s1, lo1, pf1, h1c);

    // hh2 = h1cat @ W2
    k_gemm<0><<<dim3(F2 / 64, NJ / 64), 256>>>(NJ, F1, F2, h1c, W2, nullptr, hh2);

    // Layer 2
    k_st<D2, F2><<<NJ * HH / 4, 128>>>(hh2, a_src2, a_dst2, s2, pk2);
    k_rank<<<dim3(HH, NJ / 96), 768>>>(pk2, s2, ts2, pm2, lo2);
    k_chunkv<D2, F2, 2><<<dim3(HH, NCHUNK), 2 * 2 * C2>>>(hh2, ts2, pm2, cs2, cg2);
    k_scanv<D2, F2, 2><<<dim3(HH, NCHUNK + 1), 2 * 2 * C2>>>(hh2, ts2, pm2, cs2, cg2, pf2);
    k_query2<<<NJ, F2>>>(s2, lo2, pf2, obs, gg);

    // Dense head
    k_gemm<1><<<dim3(128 / 64, NJ / 64), 256>>>(NJ, GOUT, 128, gg, P1, b1, f1);
    k_gemm<1><<<dim3(HID / 64, NJ / 64), 256>>>(NJ, 128, HID, f1, P2, b2, f2);

    // pool + mask passthrough
    int mrem = out_size - BATCH * HID;
    int mc = 0;
    if (mrem > 0 && n_in > 1) mc = in_sizes[1] < mrem ? in_sizes[1] : mrem;
    k_pool_copy<<<BATCH + (mc + 255) / 256, 256>>>(f2, mask, out, mc);
}